// round 16
// baseline (speedup 1.0000x reference)
#include <cuda_runtime.h>
#include <cuda_bf16.h>
#include <math.h>
#include <stdint.h>

// ===========================================================================
// BondPredictor: HMMA (mma.sync bf16) GEMMs via bf16x3 split precision.
// Node-space hoisting (merged P12Q, R) + epilogue gathers + one-hot embed.
// h_e kept as bf16 hi/lo planes only (plane-accumulate residual).
// 2-stage cp.async pipeline, single-sync mainloop, 64KB smem (3 CTAs/SM).
// N=20000 nodes, E=200000 edges, ND=256, ED=128, L=2, NE=5.
// ===========================================================================

#define N_MAX 20000
#define E_MAX 200000
#define NH_MAX (E_MAX / 2)

// ------------------------- fp32 scratch -----------------------------------
__device__ float g_hn  [(size_t)N_MAX * 256];
__device__ float g_agg [(size_t)N_MAX * 256];
__device__ float g_P12Q[(size_t)N_MAX * 512];   // [P1 | P2 | Q]; reused as R

// ------------------------- bf16 hi/lo planes (activations) -----------------
__device__ __nv_bfloat16 g_hn_h  [(size_t)N_MAX * 256];
__device__ __nv_bfloat16 g_hn_l  [(size_t)N_MAX * 256];
__device__ __nv_bfloat16 g_he_h  [(size_t)E_MAX * 128];
__device__ __nv_bfloat16 g_he_l  [(size_t)E_MAX * 128];
__device__ __nv_bfloat16 g_hide_h[(size_t)E_MAX * 128];
__device__ __nv_bfloat16 g_hide_l[(size_t)E_MAX * 128];
__device__ __nv_bfloat16 g_agg_h [(size_t)N_MAX * 256];
__device__ __nv_bfloat16 g_agg_l [(size_t)N_MAX * 256];
__device__ __nv_bfloat16 g_hidn_h[(size_t)N_MAX * 256];
__device__ __nv_bfloat16 g_hidn_l[(size_t)N_MAX * 256];
__device__ __nv_bfloat16 g_exte_h[(size_t)E_MAX * 64];
__device__ __nv_bfloat16 g_exte_l[(size_t)E_MAX * 64];
__device__ __nv_bfloat16 g_extn_h[(size_t)N_MAX * 64];
__device__ __nv_bfloat16 g_extn_l[(size_t)N_MAX * 64];
__device__ __nv_bfloat16 g_sym_h [(size_t)NH_MAX * 128];
__device__ __nv_bfloat16 g_sym_l [(size_t)NH_MAX * 128];
__device__ __nv_bfloat16 g_dec1_h[(size_t)NH_MAX * 128];
__device__ __nv_bfloat16 g_dec1_l[(size_t)NH_MAX * 128];

// ------------------------- transposed+split weights [N, ld] ----------------
__device__ __nv_bfloat16 g_We1t_h[2 * 128 * 704];
__device__ __nv_bfloat16 g_We1t_l[2 * 128 * 704];
__device__ __nv_bfloat16 g_We2t_h[2 * 128 * 128];
__device__ __nv_bfloat16 g_We2t_l[2 * 128 * 128];
__device__ __nv_bfloat16 g_Wmt_h [2 * 256 * 384];
__device__ __nv_bfloat16 g_Wmt_l [2 * 256 * 384];
__device__ __nv_bfloat16 g_Wn1t_h[2 * 256 * 576];
__device__ __nv_bfloat16 g_Wn1t_l[2 * 256 * 576];
__device__ __nv_bfloat16 g_Wn2t_h[2 * 256 * 256];
__device__ __nv_bfloat16 g_Wn2t_l[2 * 256 * 256];
__device__ __nv_bfloat16 g_Wd1t_h[128 * 384];
__device__ __nv_bfloat16 g_Wd1t_l[128 * 384];
__device__ __nv_bfloat16 g_Wd2t_h[128 * 128];
__device__ __nv_bfloat16 g_Wd2t_l[128 * 128];
// combined node-GEMM weight: rows 0-127 = We1[128:384]^T, 128-255 = We1[384:640]^T,
// 256-511 = Wm[0:256]^T  (per layer)
__device__ __nv_bfloat16 g_Wpq_h [2 * 512 * 256];
__device__ __nv_bfloat16 g_Wpq_l [2 * 512 * 256];

// ===========================================================================
// PTX helpers (sm_80-era: valid on plain sm_103 target)
// ===========================================================================
__device__ __forceinline__ uint32_t smem_u32(const void* p) {
    uint32_t a;
    asm("{ .reg .u64 t; cvta.to.shared.u64 t, %1; cvt.u32.u64 %0, t; }"
        : "=r"(a) : "l"(p));
    return a;
}
__device__ __forceinline__ void cp16(uint32_t dst, const void* src) {
    asm volatile("cp.async.cg.shared.global [%0], [%1], 16;" :: "r"(dst), "l"(src));
}
#define CP_COMMIT()  asm volatile("cp.async.commit_group;" ::: "memory")
#define CP_WAIT(n)   asm volatile("cp.async.wait_group %0;" :: "n"(n) : "memory")

#define LDSM4(r0, r1, r2, r3, addr) \
    asm volatile("ldmatrix.sync.aligned.m8n8.x4.shared.b16 {%0,%1,%2,%3}, [%4];" \
                 : "=r"(r0), "=r"(r1), "=r"(r2), "=r"(r3) : "r"(addr))

#define MMA16816(d, a, b0, b1) \
    asm volatile("mma.sync.aligned.m16n8k16.row.col.f32.bf16.bf16.f32 " \
                 "{%0,%1,%2,%3},{%4,%5,%6,%7},{%8,%9},{%0,%1,%2,%3};" \
                 : "+f"((d)[0]), "+f"((d)[1]), "+f"((d)[2]), "+f"((d)[3]) \
                 : "r"((a)[0]), "r"((a)[1]), "r"((a)[2]), "r"((a)[3]), \
                   "r"(b0), "r"(b1))

__device__ __forceinline__ void bf16_split(float x, __nv_bfloat16& h, __nv_bfloat16& l) {
    h = __float2bfloat16(x);
    l = __float2bfloat16(x - __bfloat162float(h));
}

// ===========================================================================
// Multi-segment HMMA GEMM (bf16x3), 2-stage cp.async, ONE sync per chunk.
//   - per-segment B column offset (boff) into a [Nout, ldb] weight
//   - epilogue gather-adds (G1/G2), scatter-atomic, fused 128->5 projection,
//     fp32 C, bf16 hi-lo planes; accum==2 accumulates from planes (hi+lo)
// smem: A bufs 2x16KB @0, B bufs 2x16KB @32768 -> 64KB (3 CTAs/SM).
// ===========================================================================
#define TG_SMEM_BYTES 65536

struct Seg { const __nv_bfloat16* h; const __nv_bfloat16* l; const int* g;
             int K; int off; int boff; };
struct SegList { Seg s[4]; int n; int Ktot; };
struct GAdd { const float* G1; const int* gi1; int gs1, go1;
              const float* G2; const int* gi2; int gs2, go2; };

__global__ __launch_bounds__(256)
void tgemm_kernel(SegList segs,
                  const __nv_bfloat16* __restrict__ Bhi,   // [Nout, ldb]
                  const __nv_bfloat16* __restrict__ Blo,
                  int ldb,
                  GAdd ga,
                  const float* __restrict__ bias,
                  float* __restrict__ C,
                  __nv_bfloat16* __restrict__ Chi,
                  __nv_bfloat16* __restrict__ Clo,
                  int M, int Nfull, int relu, int accum,
                  const int* __restrict__ scat,
                  const float* __restrict__ Wd3,
                  const float* __restrict__ bd3,
                  float* __restrict__ out5)
{
    extern __shared__ char smem[];
    const uint32_t sbase = smem_u32(smem);
    const int tid = threadIdx.x;
    const int L   = tid & 31;
    const int wid = tid >> 5;
    const int wm  = wid >> 1;      // 0..3
    const int wn  = wid & 1;       // 0..1
    const int bn0 = blockIdx.x * 128;
    const int bm0 = blockIdx.y * 128;
    const int Ktot = segs.Ktot;

    // ---- staging setup: thread -> (row srow 0..127, half sh 0..1) ----
    const int srow = tid >> 1;
    const int sh   = tid & 1;
    uint32_t soff[4];
#pragma unroll
    for (int i = 0; i < 4; i++) {
        int ch = sh * 4 + i;
        soff[i] = (uint32_t)(srow * 128 + ((ch ^ (srow & 7)) * 16));
    }
    const int arow_g = bm0 + srow;
    const __nv_bfloat16* ah[4];
    const __nv_bfloat16* al[4];
#pragma unroll
    for (int s = 0; s < 4; s++) {
        if (s < segs.n) {
            int gr = 0;
            if (arow_g < M) gr = segs.s[s].g ? segs.s[s].g[arow_g] : arow_g;
            ah[s] = segs.s[s].h + (size_t)gr * segs.s[s].K + sh * 32;
            al[s] = segs.s[s].l + (size_t)gr * segs.s[s].K + sh * 32;
        } else {
            ah[s] = segs.s[0].h;
            al[s] = segs.s[0].l;
        }
    }
    const size_t brow = (size_t)(bn0 + srow) * ldb + sh * 32;

    const int per = Ktot / 64;     // chunks per pass
    const int nch = 3 * per;

    // ---- ldmatrix per-lane address precompute ----
    uint32_t a_rbase[2], b_rbase[4];
    int a_rsw[2], b_rsw[4];
    const int a_csel = L >> 4;
    const int b_csel = (L >> 3) & 1;
#pragma unroll
    for (int mf = 0; mf < 2; mf++) {
        int r = wm * 32 + mf * 16 + ((L >> 3) & 1) * 8 + (L & 7);
        a_rbase[mf] = (uint32_t)(r * 128);
        a_rsw[mf] = r & 7;
    }
#pragma unroll
    for (int nf2 = 0; nf2 < 4; nf2++) {
        int r = wn * 64 + nf2 * 16 + (L >> 4) * 8 + (L & 7);
        b_rbase[nf2] = (uint32_t)(r * 128);
        b_rsw[nf2] = r & 7;
    }

    float acc[2][8][4];
#pragma unroll
    for (int mf = 0; mf < 2; mf++)
#pragma unroll
        for (int nf = 0; nf < 8; nf++)
#pragma unroll
            for (int q = 0; q < 4; q++) acc[mf][nf][q] = 0.0f;

    auto stage = [&](int c) {
        const int bufsel = c & 1;
        const int p  = c / per;
        const int k0 = (c - p * per) * 64;
        int s = 0;
#pragma unroll
        for (int q = 1; q < 4; q++)
            if (k0 >= segs.s[q].off) s = q;   // unused segs: off = Ktot sentinel
        const int lk = k0 - segs.s[s].off;
        const __nv_bfloat16* as = ((p == 2) ? al[s] : ah[s]) + lk;
        const __nv_bfloat16* Bb0 = (p == 1) ? Blo : Bhi;
        const __nv_bfloat16* bs = Bb0 + brow + segs.s[s].boff + lk;
        const uint32_t ab = sbase + bufsel * 16384;
        const uint32_t bb = sbase + 32768 + bufsel * 16384;
#pragma unroll
        for (int i = 0; i < 4; i++) {
            cp16(ab + soff[i], as + i * 8);
            cp16(bb + soff[i], bs + i * 8);
        }
        CP_COMMIT();
    };

    stage(0);

    for (int c = 0; c < nch; c++) {
        CP_WAIT(0);          // chunk c data landed (only group in flight)
        __syncthreads();     // all warps done with chunk c-1 -> buf (c+1)&1 free
        if (c + 1 < nch) stage(c + 1);

        const int buf = c & 1;
        const uint32_t Ab = sbase + buf * 16384;
        const uint32_t Bb = sbase + 32768 + buf * 16384;
#pragma unroll
        for (int j = 0; j < 4; j++) {
            uint32_t a0[4], a1[4];
            {
                uint32_t ca = (uint32_t)(((2 * j + a_csel) ^ a_rsw[0]) * 16);
                LDSM4(a0[0], a0[1], a0[2], a0[3], Ab + a_rbase[0] + ca);
                uint32_t cb = (uint32_t)(((2 * j + a_csel) ^ a_rsw[1]) * 16);
                LDSM4(a1[0], a1[1], a1[2], a1[3], Ab + a_rbase[1] + cb);
            }
            uint32_t bv[4][4];
#pragma unroll
            for (int nf2 = 0; nf2 < 4; nf2++) {
                uint32_t cb = (uint32_t)(((2 * j + b_csel) ^ b_rsw[nf2]) * 16);
                LDSM4(bv[nf2][0], bv[nf2][1], bv[nf2][2], bv[nf2][3],
                      Bb + b_rbase[nf2] + cb);
            }
#pragma unroll
            for (int nf2 = 0; nf2 < 4; nf2++) {
                MMA16816(acc[0][2 * nf2],     a0, bv[nf2][0], bv[nf2][1]);
                MMA16816(acc[0][2 * nf2 + 1], a0, bv[nf2][2], bv[nf2][3]);
                MMA16816(acc[1][2 * nf2],     a1, bv[nf2][0], bv[nf2][1]);
                MMA16816(acc[1][2 * nf2 + 1], a1, bv[nf2][2], bv[nf2][3]);
            }
        }
    }
    __syncthreads();   // all compute done before Cs smem reuse

    // ---- epilogue ----
    float* Cs = (float*)smem;   // out5 staging (reuse; all threads past last sync)
#pragma unroll
    for (int mf = 0; mf < 2; mf++) {
#pragma unroll
        for (int half = 0; half < 2; half++) {
            const int m = bm0 + wm * 32 + mf * 16 + (L >> 2) + half * 8;
            if (m >= M) continue;
            const float* g1r = ga.G1 ? ga.G1 + (size_t)ga.gi1[m] * ga.gs1 + ga.go1
                                     : nullptr;
            const float* g2r = ga.G2 ? ga.G2 + (size_t)ga.gi2[m] * ga.gs2 + ga.go2
                                     : nullptr;
            float* srowp = scat ? &C[(size_t)scat[m] * Nfull] : nullptr;
#pragma unroll
            for (int nf = 0; nf < 8; nf++) {
                const int col = bn0 + wn * 64 + nf * 8 + (L & 3) * 2;
                float v0 = acc[mf][nf][half * 2 + 0];
                float v1 = acc[mf][nf][half * 2 + 1];
                if (g1r) { v0 += g1r[col]; v1 += g1r[col + 1]; }
                if (g2r) { v0 += g2r[col]; v1 += g2r[col + 1]; }
                if (bias) { v0 += bias[col]; v1 += bias[col + 1]; }
                if (scat) {
                    v0 = fmaxf(v0, 0.f); v1 = fmaxf(v1, 0.f);
                    if (v0 != 0.0f) atomicAdd(srowp + col, v0);
                    if (v1 != 0.0f) atomicAdd(srowp + col + 1, v1);
                    continue;
                }
                const size_t o = (size_t)m * Nfull + col;
                if (accum == 1 && C) { v0 += C[o]; v1 += C[o + 1]; }
                if (accum == 2) {
                    v0 += __bfloat162float(Chi[o]) + __bfloat162float(Clo[o]);
                    v1 += __bfloat162float(Chi[o + 1]) + __bfloat162float(Clo[o + 1]);
                }
                if (relu) { v0 = fmaxf(v0, 0.f); v1 = fmaxf(v1, 0.f); }
                if (out5) {
                    Cs[(m - bm0) * 128 + (col - bn0)] = v0;
                    Cs[(m - bm0) * 128 + (col - bn0) + 1] = v1;
                    continue;
                }
                if (C) { C[o] = v0; C[o + 1] = v1; }
                if (Chi) {
                    __nv_bfloat16 h0, l0, h1, l1;
                    bf16_split(v0, h0, l0);
                    bf16_split(v1, h1, l1);
                    Chi[o] = h0; Chi[o + 1] = h1;
                    Clo[o] = l0; Clo[o + 1] = l1;
                }
            }
        }
    }

    // ---- fused final projection (128 -> 5), only when out5 set ----
    if (out5) {
        __syncthreads();
        if (tid < 128) {
            const int m = bm0 + tid;
            if (m < M) {
                const float* row = &Cs[tid * 128];
                float s0 = bd3[0], s1 = bd3[1], s2 = bd3[2], s3 = bd3[3], s4 = bd3[4];
#pragma unroll 8
                for (int k = 0; k < 128; k++) {
                    float x = row[k];
                    const float* w = &Wd3[k * 5];
                    s0 = fmaf(x, w[0], s0);
                    s1 = fmaf(x, w[1], s1);
                    s2 = fmaf(x, w[2], s2);
                    s3 = fmaf(x, w[3], s3);
                    s4 = fmaf(x, w[4], s4);
                }
                float* op = &out5[(size_t)m * 5];
                op[0] = s0; op[1] = s1; op[2] = s2; op[3] = s3; op[4] = s4;
            }
        }
    }
}

// ===========================================================================
// Batched weight transpose + split: W[K,N] fp32 -> Th/Tl [N, ldt] bf16 (padded)
// ===========================================================================
struct WJob { const float* W; int K, N, ldt; __nv_bfloat16* Th; __nv_bfloat16* Tl; };
struct WJobs { WJob j[18]; };

__global__ void wt_conv_all(WJobs jobs)
{
    const WJob jb = jobs.j[blockIdx.z];
    const int n0 = blockIdx.x * 32;
    const int k0 = blockIdx.y * 32;
    if (n0 >= jb.N || k0 >= jb.ldt) return;
    __shared__ float tile[32][33];
    const int tx = threadIdx.x, ty = threadIdx.y;  // 32x8
    for (int i = ty; i < 32; i += 8) {
        int k = k0 + i, n = n0 + tx;
        tile[i][tx] = (k < jb.K && n < jb.N) ? jb.W[(size_t)k * jb.N + n] : 0.0f;
    }
    __syncthreads();
    for (int i = ty; i < 32; i += 8) {
        int n = n0 + i, k = k0 + tx;
        if (n < jb.N && k < jb.ldt) {
            float x = tile[tx][i];
            __nv_bfloat16 hb, lb;
            bf16_split(x, hb, lb);
            jb.Th[(size_t)n * jb.ldt + k] = hb;
            jb.Tl[(size_t)n * jb.ldt + k] = lb;
        }
    }
}

// fp32 -> hi/lo planes; also re-zeroes the source (agg reuse across layers)
__global__ void act_conv_kernel(float* __restrict__ X,
                                __nv_bfloat16* __restrict__ Xh,
                                __nv_bfloat16* __restrict__ Xl, int n4)
{
    int i = blockIdx.x * 256 + threadIdx.x;
    if (i >= n4) return;
    float4 x = ((float4*)X)[i];
    __nv_bfloat16 hh[4], ll[4];
    bf16_split(x.x, hh[0], ll[0]);
    bf16_split(x.y, hh[1], ll[1]);
    bf16_split(x.z, hh[2], ll[2]);
    bf16_split(x.w, hh[3], ll[3]);
    *(uint2*)(Xh + (size_t)i * 4) = *(uint2*)hh;
    *(uint2*)(Xl + (size_t)i * 4) = *(uint2*)ll;
    ((float4*)X)[i] = make_float4(0.f, 0.f, 0.f, 0.f);
}

// ===========================================================================
// Elementwise / small kernels
// ===========================================================================

__global__ void init_node_kernel(const float* __restrict__ h_node,
                                 const int* __restrict__ batch_node,
                                 const int* __restrict__ t,
                                 const float* __restrict__ Wne,
                                 float* __restrict__ hn,
                                 __nv_bfloat16* __restrict__ hn_h,
                                 __nv_bfloat16* __restrict__ hn_l,
                                 __nv_bfloat16* __restrict__ extn_h,
                                 __nv_bfloat16* __restrict__ extn_l)
{
    int row = blockIdx.x;
    int c = threadIdx.x;  // 256
    __shared__ float tn_s;
    __shared__ int ty_s;
    if (c == 0) tn_s = (float)t[batch_node[row]];
    if (c < 16) { if (h_node[row * 16 + c] != 0.0f) ty_s = c; }  // one-hot: single writer
    __syncthreads();
    float tn = tn_s;
    float v;
    if (c < 240) {
        v = Wne[ty_s * 240 + c];   // one-hot row gather
    } else {
        const float step = 1000.0f / 15.0f;
        float dx = tn - (float)(c - 240) * step;
        v = expf((-0.5f / (step * step)) * dx * dx);
    }
    size_t idx = (size_t)row * 256 + c;
    hn[idx] = v;
    __nv_bfloat16 hb, lb; bf16_split(v, hb, lb);
    hn_h[idx] = hb; hn_l[idx] = lb;
    if (c < 64) {
        float ev = (c == 0) ? tn * (1.0f / 1000.0f) : 0.0f;
        __nv_bfloat16 eh, el; bf16_split(ev, eh, el);
        extn_h[(size_t)row * 64 + c] = eh;
        extn_l[(size_t)row * 64 + c] = el;
    }
}

// warp-per-edge: block = 256 threads = 8 edges. One-hot via ballot; no he fp32.
__global__ void init_edge_kernel(const float* __restrict__ h_node,
                                 const float* __restrict__ pos,
                                 const int* __restrict__ ei,
                                 const int* __restrict__ batch_edge,
                                 const int* __restrict__ t,
                                 const float* __restrict__ Wee,
                                 __nv_bfloat16* __restrict__ he_h,
                                 __nv_bfloat16* __restrict__ he_l,
                                 __nv_bfloat16* __restrict__ exte_h,
                                 __nv_bfloat16* __restrict__ exte_l,
                                 int E)
{
    const int e = blockIdx.x * 8 + (threadIdx.x >> 5);
    const int L = threadIdx.x & 31;
    if (e >= E) return;
    const int s = ei[e], d = ei[E + e];

    // one-hot type detection via ballot (lanes 0-15: src, 16-31: dst)
    const float hv = (L < 16) ? h_node[s * 16 + L] : h_node[d * 16 + (L - 16)];
    const unsigned bm = __ballot_sync(0xffffffffu, hv != 0.0f);
    const int ts = __ffs(bm & 0xffffu) - 1;
    const int td = __ffs(bm >> 16) - 1;

    const float te = (float)t[batch_edge[e]];
    const float dx = pos[d * 3 + 0] - pos[s * 3 + 0];
    const float dy = pos[d * 3 + 1] - pos[s * 3 + 1];
    const float dz = pos[d * 3 + 2] - pos[s * 3 + 2];
    const float dd = sqrtf(dx * dx + dy * dy + dz * dz);

    const int c0 = L * 4;                 // this lane's 4 columns
    float v[4];
    if (c0 < 112) {
        float4 ws = *(const float4*)&Wee[ts * 112 + c0];
        float4 wd = *(const float4*)&Wee[(16 + td) * 112 + c0];
        v[0] = ws.x + wd.x; v[1] = ws.y + wd.y;
        v[2] = ws.z + wd.z; v[3] = ws.w + wd.w;
    } else {
        const float step = 1000.0f / 15.0f;
        const float cf = -0.5f / (step * step);
#pragma unroll
        for (int i = 0; i < 4; i++) {
            float dt = te - (float)(c0 + i - 112) * step;
            v[i] = expf(cf * dt * dt);
        }
    }
    const size_t idx = (size_t)e * 128 + c0;
    __nv_bfloat16 hh[4], ll[4];
#pragma unroll
    for (int i = 0; i < 4; i++) bf16_split(v[i], hh[i], ll[i]);
    *(uint2*)&he_h[idx] = *(uint2*)hh;
    *(uint2*)&he_l[idx] = *(uint2*)ll;

    if (L < 16) {
        float ev[4];
#pragma unroll
        for (int i = 0; i < 4; i++) {
            int c = c0 + i;
            if (c < 16) {
                const float step = 10.0f / 15.0f;
                float dv = dd - (float)c * step;
                ev[i] = expf((-0.5f / (step * step)) * dv * dv);
            } else if (c == 16) {
                ev[i] = te * (1.0f / 1000.0f);
            } else {
                ev[i] = 0.0f;
            }
        }
        __nv_bfloat16 eh[4], el[4];
#pragma unroll
        for (int i = 0; i < 4; i++) bf16_split(ev[i], eh[i], el[i]);
        const size_t eidx = (size_t)e * 64 + c0;
        *(uint2*)&exte_h[eidx] = *(uint2*)eh;
        *(uint2*)&exte_l[eidx] = *(uint2*)el;
    }
}

__global__ void zero_kernel(float* __restrict__ p, int n)
{
    int i = blockIdx.x * 256 + threadIdx.x;
    if (i < n) p[i] = 0.0f;
}

// sym planes from he planes (reconstruct hi+lo)
__global__ void sym_kernel(const __nv_bfloat16* __restrict__ heh,
                           const __nv_bfloat16* __restrict__ hel,
                           __nv_bfloat16* __restrict__ oh,
                           __nv_bfloat16* __restrict__ ol, int nh)
{
    size_t i = (size_t)blockIdx.x * 256 + threadIdx.x;
    if (i >= (size_t)nh * 128) return;
    size_t j = i + (size_t)nh * 128;
    float v = __bfloat162float(heh[i]) + __bfloat162float(hel[i])
            + __bfloat162float(heh[j]) + __bfloat162float(hel[j]);
    __nv_bfloat16 hb, lb; bf16_split(v, hb, lb);
    oh[i] = hb; ol[i] = lb;
}

// ===========================================================================
// Host side
// ===========================================================================
template <typename T>
static T* sym_addr(T* symbol)
{
    void* p = nullptr;
    cudaGetSymbolAddress(&p, (const void*)symbol);
    return (T*)p;
}

static SegList make_segs(int n,
                         const __nv_bfloat16* h0, const __nv_bfloat16* l0, const int* g0, int K0,
                         const __nv_bfloat16* h1 = nullptr, const __nv_bfloat16* l1 = nullptr,
                         const int* g1 = nullptr, int K1 = 0,
                         const __nv_bfloat16* h2 = nullptr, const __nv_bfloat16* l2 = nullptr,
                         const int* g2 = nullptr, int K2 = 0)
{
    SegList sl;
    sl.s[0] = {h0, l0, g0, K0, 0, 0};
    sl.s[1] = {h1, l1, g1, K1, 0, 0};
    sl.s[2] = {h2, l2, g2, K2, 0, 0};
    sl.s[3] = {h0, l0, nullptr, K0, 0, 0};
    sl.n = n;
    int off = 0;
    for (int i = 0; i < 3; i++) {
        if (i < n) { sl.s[i].off = off; sl.s[i].boff = off; off += sl.s[i].K; }
    }
    sl.Ktot = off;
    for (int i = n; i < 4; i++) sl.s[i].off = off;   // sentinel: never selected
    return sl;
}

static GAdd make_gadd(const float* G1 = nullptr, const int* gi1 = nullptr,
                      int gs1 = 0, int go1 = 0,
                      const float* G2 = nullptr, const int* gi2 = nullptr,
                      int gs2 = 0, int go2 = 0)
{
    return GAdd{G1, gi1, gs1, go1, G2, gi2, gs2, go2};
}

static void launch_tgemm(const SegList& segs,
                         const __nv_bfloat16* Bh, const __nv_bfloat16* Bl, int ldb,
                         const GAdd& ga,
                         const float* bias, float* C,
                         __nv_bfloat16* Ch, __nv_bfloat16* Cl,
                         int M, int Nfull, int relu, int accum,
                         const int* scat = nullptr,
                         const float* Wd3 = nullptr, const float* bd3 = nullptr,
                         float* out5 = nullptr)
{
    dim3 grid(Nfull / 128, (M + 127) / 128);
    tgemm_kernel<<<grid, 256, TG_SMEM_BYTES>>>(segs, Bh, Bl, ldb, ga, bias,
                                               C, Ch, Cl, M, Nfull, relu, accum,
                                               scat, Wd3, bd3, out5);
}

extern "C" void kernel_launch(void* const* d_in, const int* in_sizes, int n_in,
                              void* d_out, int out_size)
{
    cudaFuncSetAttribute(tgemm_kernel, cudaFuncAttributeMaxDynamicSharedMemorySize,
                         TG_SMEM_BYTES);

    const float* h_node     = (const float*)d_in[0];
    const float* pos        = (const float*)d_in[1];
    const int*   batch_node = (const int*)  d_in[2];
    const int*   ei         = (const int*)  d_in[3];
    const int*   batch_edge = (const int*)  d_in[4];
    const int*   t          = (const int*)  d_in[5];
    const float* Wne = (const float*)d_in[6];
    const float* Wee = (const float*)d_in[7];
    const float* We1 = (const float*)d_in[8];
    const float* be1 = (const float*)d_in[9];
    const float* We2 = (const float*)d_in[10];
    const float* be2 = (const float*)d_in[11];
    const float* Wm  = (const float*)d_in[12];
    const float* bm  = (const float*)d_in[13];
    const float* Wn1 = (const float*)d_in[14];
    const float* bn1 = (const float*)d_in[15];
    const float* Wn2 = (const float*)d_in[16];
    const float* bn2 = (const float*)d_in[17];
    const float* Wd1 = (const float*)d_in[18];
    const float* bd1 = (const float*)d_in[19];
    const float* Wd2 = (const float*)d_in[20];
    const float* bd2 = (const float*)d_in[21];
    const float* Wd3 = (const float*)d_in[22];
    const float* bd3 = (const float*)d_in[23];

    const int N  = in_sizes[0] / 16;   // 20000
    const int E  = in_sizes[4];        // 200000
    const int nh = E / 2;              // 100000
    const int* src = ei;
    const int* dst = ei + E;

    float* hn   = sym_addr(g_hn);
    float* agg  = sym_addr(g_agg);
    float* P12Q = sym_addr(g_P12Q);
    float* R    = P12Q;   // decode reuse ([N,128])

    __nv_bfloat16 *hn_h = sym_addr(g_hn_h), *hn_l = sym_addr(g_hn_l);
    __nv_bfloat16 *he_h = sym_addr(g_he_h), *he_l = sym_addr(g_he_l);
    __nv_bfloat16 *hide_h = sym_addr(g_hide_h), *hide_l = sym_addr(g_hide_l);
    __nv_bfloat16 *agg_h = sym_addr(g_agg_h), *agg_l = sym_addr(g_agg_l);
    __nv_bfloat16 *hidn_h = sym_addr(g_hidn_h), *hidn_l = sym_addr(g_hidn_l);
    __nv_bfloat16 *exte_h = sym_addr(g_exte_h), *exte_l = sym_addr(g_exte_l);
    __nv_bfloat16 *extn_h = sym_addr(g_extn_h), *extn_l = sym_addr(g_extn_l);
    __nv_bfloat16 *symh = sym_addr(g_sym_h), *syml = sym_addr(g_sym_l);
    __nv_bfloat16 *dec1_h = sym_addr(g_dec1_h), *dec1_l = sym_addr(g_dec1_l);

    __nv_bfloat16 *We1t_h = sym_addr(g_We1t_h), *We1t_l = sym_addr(g_We1t_l);
    __nv_bfloat16 *We2t_h = sym_addr(g_We2t_h), *We2t_l = sym_addr(g_We2t_l);
    __nv_bfloat16 *Wmt_h  = sym_addr(g_Wmt_h),  *Wmt_l  = sym_addr(g_Wmt_l);
    __nv_bfloat16 *Wn1t_h = sym_addr(g_Wn1t_h), *Wn1t_l = sym_addr(g_Wn1t_l);
    __nv_bfloat16 *Wn2t_h = sym_addr(g_Wn2t_h), *Wn2t_l = sym_addr(g_Wn2t_l);
    __nv_bfloat16 *Wd1t_h = sym_addr(g_Wd1t_h), *Wd1t_l = sym_addr(g_Wd1t_l);
    __nv_bfloat16 *Wd2t_h = sym_addr(g_Wd2t_h), *Wd2t_l = sym_addr(g_Wd2t_l);
    __nv_bfloat16 *Wpq_h  = sym_addr(g_Wpq_h),  *Wpq_l  = sym_addr(g_Wpq_l);

    // --- weight transpose + split: ONE batched launch (18 jobs) ---
    {
        WJobs J;
        int q = 0;
        for (int l = 0; l < 2; l++) {
            const float* We1l = We1 + (size_t)l * 657 * 128;
            J.j[q++] = {We1l, 657, 128, 704,
                        We1t_h + (size_t)l * 128 * 704, We1t_l + (size_t)l * 128 * 704};
            J.j[q++] = {We2 + (size_t)l * 128 * 128, 128, 128, 128,
                        We2t_h + (size_t)l * 128 * 128, We2t_l + (size_t)l * 128 * 128};
            J.j[q++] = {Wm + (size_t)l * 384 * 256, 384, 256, 384,
                        Wmt_h + (size_t)l * 256 * 384, Wmt_l + (size_t)l * 256 * 384};
            J.j[q++] = {Wn1 + (size_t)l * 513 * 256, 513, 256, 576,
                        Wn1t_h + (size_t)l * 256 * 576, Wn1t_l + (size_t)l * 256 * 576};
            J.j[q++] = {Wn2 + (size_t)l * 256 * 256, 256, 256, 256,
                        Wn2t_h + (size_t)l * 256 * 256, Wn2t_l + (size_t)l * 256 * 256};
            __nv_bfloat16* ph = Wpq_h + (size_t)l * 512 * 256;
            __nv_bfloat16* pl = Wpq_l + (size_t)l * 512 * 256;
            J.j[q++] = {We1l + (size_t)128 * 128, 256, 128, 256, ph, pl};
            J.j[q++] = {We1l + (size_t)384 * 128, 256, 128, 256,
                        ph + (size_t)128 * 256, pl + (size_t)128 * 256};
            J.j[q++] = {Wm + (size_t)l * 384 * 256, 256, 256, 256,
                        ph + (size_t)256 * 256, pl + (size_t)256 * 256};
        }
        J.j[q++] = {Wd1, 384, 128, 384, Wd1t_h, Wd1t_l};
        J.j[q++] = {Wd2, 128, 128, 128, Wd2t_h, Wd2t_l};
        wt_conv_all<<<dim3(8, 22, 18), dim3(32, 8)>>>(J);
    }

    // --- embeddings (one-hot lookup, inline type detection) ---
    init_node_kernel<<<N, 256>>>(h_node, batch_node, t, Wne, hn, hn_h, hn_l,
                                 extn_h, extn_l);
    init_edge_kernel<<<(E + 7) / 8, 256>>>(h_node, pos, ei, batch_edge, t, Wee,
                                           he_h, he_l, exte_h, exte_l, E);

    const GAdd noG = make_gadd();

    // --- L = 2 NodeEdgeNet blocks ---
    for (int l = 0; l < 2; l++) {
        const float* be1l = be1 + (size_t)l * 128;
        const float* be2l = be2 + (size_t)l * 128;
        const float* bml  = bm  + (size_t)l * 256;
        const float* bn1l = bn1 + (size_t)l * 256;
        const float* bn2l = bn2 + (size_t)l * 256;

        const __nv_bfloat16* We1th = We1t_h + (size_t)l * 128 * 704;
        const __nv_bfloat16* We1tl = We1t_l + (size_t)l * 128 * 704;
        const __nv_bfloat16* We2th = We2t_h + (size_t)l * 128 * 128;
        const __nv_bfloat16* We2tl = We2t_l + (size_t)l * 128 * 128;
        const __nv_bfloat16* Wmth  = Wmt_h  + (size_t)l * 256 * 384;
        const __nv_bfloat16* Wmtl  = Wmt_l  + (size_t)l * 256 * 384;
        const __nv_bfloat16* Wn1th = Wn1t_h + (size_t)l * 256 * 576;
        const __nv_bfloat16* Wn1tl = Wn1t_l + (size_t)l * 256 * 576;
        const __nv_bfloat16* Wn2th = Wn2t_h + (size_t)l * 256 * 256;
        const __nv_bfloat16* Wn2tl = Wn2t_l + (size_t)l * 256 * 256;
        const __nv_bfloat16* Wpqh  = Wpq_h  + (size_t)l * 512 * 256;
        const __nv_bfloat16* Wpql  = Wpq_l  + (size_t)l * 512 * 256;

        // P12Q = hn @ [We1[128:384] | We1[384:640] | Wm[0:256]]  (N x 512)
        launch_tgemm(make_segs(1, hn_h, hn_l, nullptr, 256),
                     Wpqh, Wpql, 256, noG, nullptr, P12Q, nullptr, nullptr,
                     N, 512, 0, 0);

        // hidden_e = relu(he@W0 + ext@W3 + P1[src] + P2[dst] + be1) -> planes
        {
            SegList se = make_segs(2,
                                   he_h, he_l, nullptr, 128,
                                   exte_h, exte_l, nullptr, 64);
            se.s[1].boff = 640;   // ext maps to We1 rows 640..704
            launch_tgemm(se, We1th, We1tl, 704,
                         make_gadd(P12Q, src, 512, 0, P12Q, dst, 512, 128),
                         be1l, nullptr, hide_h, hide_l, E, 128, 1, 0);
        }

        // agg must be zero before the first scatter (act_conv re-zeroes after)
        if (l == 0)
            zero_kernel<<<(N * 256 + 255) / 256, 256>>>(agg, N * 256);

        // h_e += hidden_e @ We2 + be2  (plane-accumulate residual, planes out)
        launch_tgemm(make_segs(1, hide_h, hide_l, nullptr, 128),
                     We2th, We2tl, 128, noG, be2l, nullptr, he_h, he_l,
                     E, 128, 0, 2);

        // agg[dst] += relu(he@Wm[256:384] + Q[src] + bm)  (fused scatter)
        {
            SegList sm = make_segs(1, he_h, he_l, nullptr, 128);
            sm.s[0].boff = 256;
            launch_tgemm(sm, Wmth, Wmtl, 384,
                         make_gadd(P12Q, src, 512, 256),
                         bml, agg, nullptr, nullptr, E, 256, 1, 0, dst);
        }

        // agg planes + re-zero agg for next layer
        act_conv_kernel<<<(N * 64 + 255) / 256, 256>>>(agg, agg_h, agg_l, N * 64);

        // hidden_n = relu([h_n | agg | ext_n] @ Wn1 + bn1) -> planes
        launch_tgemm(make_segs(3,
                         hn_h, hn_l, nullptr, 256,
                         agg_h, agg_l, nullptr, 256,
                         extn_h, extn_l, nullptr, 64),
                     Wn1th, Wn1tl, 576, noG, bn1l, nullptr, hidn_h, hidn_l,
                     N, 256, 1, 0);

        // h_n += hidden_n @ Wn2 + bn2 (residual, fp32) + planes
        launch_tgemm(make_segs(1, hidn_h, hidn_l, nullptr, 256),
                     Wn2th, Wn2tl, 256, noG, bn2l, hn, hn_h, hn_l, N, 256, 1 == 2, 1);
    }

    // --- decode ---
    // R = hn @ Wd1[128:384]  (node space; pair@W1 = R[src] + R[dst] by linearity)
    {
        SegList sr = make_segs(1, hn_h, hn_l, nullptr, 256);
        sr.s[0].boff = 128;
        launch_tgemm(sr, Wd1t_h, Wd1t_l, 384, noG, nullptr, R, nullptr, nullptr,
                     N, 128, 0, 0);
    }
    sym_kernel<<<(int)(((size_t)nh * 128 + 255) / 256), 256>>>(he_h, he_l,
                                                               symh, syml, nh);

    // dec1 = relu(sym@Wd1[0:128] + R[src] + R[dst] + bd1) -> planes
    launch_tgemm(make_segs(1, symh, syml, nullptr, 128),
                 Wd1t_h, Wd1t_l, 384,
                 make_gadd(R, src, 128, 0, R, dst, 128, 0),
                 bd1, nullptr, dec1_h, dec1_l, nh, 128, 1, 0);

    // out = relu(dec1 @ Wd2 + bd2) @ Wd3 + bd3   (fused final projection)
    launch_tgemm(make_segs(1, dec1_h, dec1_l, nullptr, 128),
                 Wd2t_h, Wd2t_l, 128, noG, bd2, nullptr, nullptr, nullptr,
                 nh, 128, 1, 0, nullptr, Wd3, bd3, (float*)d_out);
}

// round 17
// speedup vs baseline: 1.0773x; 1.0773x over previous
#include <cuda_runtime.h>
#include <cuda_bf16.h>
#include <math.h>
#include <stdint.h>

// ===========================================================================
// BondPredictor: HMMA (mma.sync bf16) GEMMs via bf16x3 split precision.
// Node-space hoisting (merged P12Q, R) + epilogue gathers + one-hot embed.
// GEMM tile 64x128 (acc 32 regs/thread -> 3 CTAs/SM), 2-stage cp.async.
// N=20000 nodes, E=200000 edges, ND=256, ED=128, L=2, NE=5.
// ===========================================================================

#define N_MAX 20000
#define E_MAX 200000
#define NH_MAX (E_MAX / 2)

// ------------------------- fp32 scratch -----------------------------------
__device__ float g_hn  [(size_t)N_MAX * 256];
__device__ float g_he  [(size_t)E_MAX * 128];
__device__ float g_agg [(size_t)N_MAX * 256];
__device__ float g_P12Q[(size_t)N_MAX * 512];   // [P1 | P2 | Q]; reused as R
__device__ int   g_ty  [N_MAX];

// ------------------------- bf16 hi/lo planes (activations) -----------------
__device__ __nv_bfloat16 g_hn_h  [(size_t)N_MAX * 256];
__device__ __nv_bfloat16 g_hn_l  [(size_t)N_MAX * 256];
__device__ __nv_bfloat16 g_he_h  [(size_t)E_MAX * 128];
__device__ __nv_bfloat16 g_he_l  [(size_t)E_MAX * 128];
__device__ __nv_bfloat16 g_hide_h[(size_t)E_MAX * 128];
__device__ __nv_bfloat16 g_hide_l[(size_t)E_MAX * 128];
__device__ __nv_bfloat16 g_agg_h [(size_t)N_MAX * 256];
__device__ __nv_bfloat16 g_agg_l [(size_t)N_MAX * 256];
__device__ __nv_bfloat16 g_hidn_h[(size_t)N_MAX * 256];
__device__ __nv_bfloat16 g_hidn_l[(size_t)N_MAX * 256];
__device__ __nv_bfloat16 g_exte_h[(size_t)E_MAX * 64];
__device__ __nv_bfloat16 g_exte_l[(size_t)E_MAX * 64];
__device__ __nv_bfloat16 g_extn_h[(size_t)N_MAX * 64];
__device__ __nv_bfloat16 g_extn_l[(size_t)N_MAX * 64];
__device__ __nv_bfloat16 g_sym_h [(size_t)NH_MAX * 128];
__device__ __nv_bfloat16 g_sym_l [(size_t)NH_MAX * 128];
__device__ __nv_bfloat16 g_dec1_h[(size_t)NH_MAX * 128];
__device__ __nv_bfloat16 g_dec1_l[(size_t)NH_MAX * 128];

// ------------------------- transposed+split weights [N, ld] ----------------
__device__ __nv_bfloat16 g_We1t_h[2 * 128 * 704];
__device__ __nv_bfloat16 g_We1t_l[2 * 128 * 704];
__device__ __nv_bfloat16 g_We2t_h[2 * 128 * 128];
__device__ __nv_bfloat16 g_We2t_l[2 * 128 * 128];
__device__ __nv_bfloat16 g_Wmt_h [2 * 256 * 384];
__device__ __nv_bfloat16 g_Wmt_l [2 * 256 * 384];
__device__ __nv_bfloat16 g_Wn1t_h[2 * 256 * 576];
__device__ __nv_bfloat16 g_Wn1t_l[2 * 256 * 576];
__device__ __nv_bfloat16 g_Wn2t_h[2 * 256 * 256];
__device__ __nv_bfloat16 g_Wn2t_l[2 * 256 * 256];
__device__ __nv_bfloat16 g_Wd1t_h[128 * 384];
__device__ __nv_bfloat16 g_Wd1t_l[128 * 384];
__device__ __nv_bfloat16 g_Wd2t_h[128 * 128];
__device__ __nv_bfloat16 g_Wd2t_l[128 * 128];
// combined node-GEMM weight: rows 0-127 = We1[128:384]^T, 128-255 = We1[384:640]^T,
// 256-511 = Wm[0:256]^T  (per layer)
__device__ __nv_bfloat16 g_Wpq_h [2 * 512 * 256];
__device__ __nv_bfloat16 g_Wpq_l [2 * 512 * 256];

// ===========================================================================
// PTX helpers (sm_80-era: valid on plain sm_103 target)
// ===========================================================================
__device__ __forceinline__ uint32_t smem_u32(const void* p) {
    uint32_t a;
    asm("{ .reg .u64 t; cvta.to.shared.u64 t, %1; cvt.u32.u64 %0, t; }"
        : "=r"(a) : "l"(p));
    return a;
}
__device__ __forceinline__ void cp16(uint32_t dst, const void* src) {
    asm volatile("cp.async.cg.shared.global [%0], [%1], 16;" :: "r"(dst), "l"(src));
}
#define CP_COMMIT()  asm volatile("cp.async.commit_group;" ::: "memory")
#define CP_WAIT(n)   asm volatile("cp.async.wait_group %0;" :: "n"(n) : "memory")

#define LDSM4(r0, r1, r2, r3, addr) \
    asm volatile("ldmatrix.sync.aligned.m8n8.x4.shared.b16 {%0,%1,%2,%3}, [%4];" \
                 : "=r"(r0), "=r"(r1), "=r"(r2), "=r"(r3) : "r"(addr))

#define MMA16816(d, a, b0, b1) \
    asm volatile("mma.sync.aligned.m16n8k16.row.col.f32.bf16.bf16.f32 " \
                 "{%0,%1,%2,%3},{%4,%5,%6,%7},{%8,%9},{%0,%1,%2,%3};" \
                 : "+f"((d)[0]), "+f"((d)[1]), "+f"((d)[2]), "+f"((d)[3]) \
                 : "r"((a)[0]), "r"((a)[1]), "r"((a)[2]), "r"((a)[3]), \
                   "r"(b0), "r"(b1))

__device__ __forceinline__ void bf16_split(float x, __nv_bfloat16& h, __nv_bfloat16& l) {
    h = __float2bfloat16(x);
    l = __float2bfloat16(x - __bfloat162float(h));
}

// ===========================================================================
// Multi-segment HMMA GEMM (bf16x3), tile 64(M) x 128(N), BK=64.
// 8 warps as 2(m) x 4(n) -> 32x32 warp tiles; acc = 32 regs/thread.
// 2-stage cp.async double buffering.
// smem: A bufs 2x8KB @0, B bufs 2x16KB @16384 -> 48KB.
// ===========================================================================
#define TG_SMEM_BYTES 49152

struct Seg { const __nv_bfloat16* h; const __nv_bfloat16* l; const int* g;
             int K; int off; int boff; };
struct SegList { Seg s[4]; int n; int Ktot; };
struct GAdd { const float* G1; const int* gi1; int gs1, go1;
              const float* G2; const int* gi2; int gs2, go2; };

__global__ __launch_bounds__(256)
void tgemm_kernel(SegList segs,
                  const __nv_bfloat16* __restrict__ Bhi,   // [Nout, ldb]
                  const __nv_bfloat16* __restrict__ Blo,
                  int ldb,
                  GAdd ga,
                  const float* __restrict__ bias,
                  float* __restrict__ C,
                  __nv_bfloat16* __restrict__ Chi,
                  __nv_bfloat16* __restrict__ Clo,
                  int M, int Nfull, int relu, int accum,
                  const int* __restrict__ scat,
                  const float* __restrict__ Wd3,
                  const float* __restrict__ bd3,
                  float* __restrict__ out5)
{
    extern __shared__ char smem[];
    const uint32_t sbase = smem_u32(smem);
    const int tid = threadIdx.x;
    const int L   = tid & 31;
    const int wid = tid >> 5;
    const int wm  = wid >> 2;      // 0..1
    const int wn  = wid & 3;       // 0..3
    const int bn0 = blockIdx.x * 128;
    const int bm0 = blockIdx.y * 64;
    const int Ktot = segs.Ktot;

    // ---- A staging: thread -> (row ar 0..63, quarter aq 0..3), 2 cp16 each ----
    const int ar = tid >> 2;
    const int aq = tid & 3;
    uint32_t soffA[2];
#pragma unroll
    for (int i = 0; i < 2; i++) {
        int ch = aq * 2 + i;
        soffA[i] = (uint32_t)(ar * 128 + ((ch ^ (ar & 7)) * 16));
    }
    // ---- B staging: thread -> (row br 0..127, half bh 0..1), 4 cp16 each ----
    const int br = tid >> 1;
    const int bh = tid & 1;
    uint32_t soffB[4];
#pragma unroll
    for (int i = 0; i < 4; i++) {
        int ch = bh * 4 + i;
        soffB[i] = (uint32_t)(br * 128 + ((ch ^ (br & 7)) * 16));
    }

    const int arow_g = bm0 + ar;
    const __nv_bfloat16* ah[4];
    const __nv_bfloat16* al[4];
#pragma unroll
    for (int s = 0; s < 4; s++) {
        if (s < segs.n) {
            int gr = 0;
            if (arow_g < M) gr = segs.s[s].g ? segs.s[s].g[arow_g] : arow_g;
            ah[s] = segs.s[s].h + (size_t)gr * segs.s[s].K + aq * 16;
            al[s] = segs.s[s].l + (size_t)gr * segs.s[s].K + aq * 16;
        } else {
            ah[s] = segs.s[0].h;
            al[s] = segs.s[0].l;
        }
    }
    const size_t brow = (size_t)(bn0 + br) * ldb + bh * 32;

    const int per = Ktot / 64;     // chunks per pass
    const int nch = 3 * per;

    // ---- ldmatrix per-lane address precompute ----
    uint32_t a_rbase[2], b_rbase[2];
    int a_rsw[2], b_rsw[2];
    const int a_csel = L >> 4;
    const int b_csel = (L >> 3) & 1;
#pragma unroll
    for (int mf = 0; mf < 2; mf++) {
        int r = wm * 32 + mf * 16 + ((L >> 3) & 1) * 8 + (L & 7);
        a_rbase[mf] = (uint32_t)(r * 128);
        a_rsw[mf] = r & 7;
    }
#pragma unroll
    for (int nf2 = 0; nf2 < 2; nf2++) {
        int r = wn * 32 + nf2 * 16 + (L >> 4) * 8 + (L & 7);
        b_rbase[nf2] = (uint32_t)(r * 128);
        b_rsw[nf2] = r & 7;
    }

    float acc[2][4][4];
#pragma unroll
    for (int mf = 0; mf < 2; mf++)
#pragma unroll
        for (int nf = 0; nf < 4; nf++)
#pragma unroll
            for (int q = 0; q < 4; q++) acc[mf][nf][q] = 0.0f;

    auto stage = [&](int c) {
        const int bufsel = c & 1;
        const int p  = c / per;
        const int k0 = (c - p * per) * 64;
        int s = 0;
#pragma unroll
        for (int q = 1; q < 4; q++)
            if (k0 >= segs.s[q].off) s = q;   // unused segs: off = Ktot sentinel
        const int lk = k0 - segs.s[s].off;
        const __nv_bfloat16* as = ((p == 2) ? al[s] : ah[s]) + lk;
        const __nv_bfloat16* Bb0 = (p == 1) ? Blo : Bhi;
        const __nv_bfloat16* bs = Bb0 + brow + segs.s[s].boff + lk;
        const uint32_t ab = sbase + bufsel * 8192;
        const uint32_t bb = sbase + 16384 + bufsel * 16384;
#pragma unroll
        for (int i = 0; i < 2; i++) cp16(ab + soffA[i], as + i * 8);
#pragma unroll
        for (int i = 0; i < 4; i++) cp16(bb + soffB[i], bs + i * 8);
        CP_COMMIT();
    };

    stage(0);

    for (int c = 0; c < nch; c++) {
        const int buf = c & 1;
        if (c + 1 < nch) { stage(c + 1); CP_WAIT(1); }
        else             { CP_WAIT(0); }
        __syncthreads();

        const uint32_t Ab = sbase + buf * 8192;
        const uint32_t Bb = sbase + 16384 + buf * 16384;
#pragma unroll
        for (int j = 0; j < 4; j++) {
            uint32_t a0[4], a1[4];
            {
                uint32_t ca = (uint32_t)(((2 * j + a_csel) ^ a_rsw[0]) * 16);
                LDSM4(a0[0], a0[1], a0[2], a0[3], Ab + a_rbase[0] + ca);
                uint32_t cb = (uint32_t)(((2 * j + a_csel) ^ a_rsw[1]) * 16);
                LDSM4(a1[0], a1[1], a1[2], a1[3], Ab + a_rbase[1] + cb);
            }
            uint32_t bv[2][4];
#pragma unroll
            for (int nf2 = 0; nf2 < 2; nf2++) {
                uint32_t cb = (uint32_t)(((2 * j + b_csel) ^ b_rsw[nf2]) * 16);
                LDSM4(bv[nf2][0], bv[nf2][1], bv[nf2][2], bv[nf2][3],
                      Bb + b_rbase[nf2] + cb);
            }
#pragma unroll
            for (int nf2 = 0; nf2 < 2; nf2++) {
                MMA16816(acc[0][2 * nf2],     a0, bv[nf2][0], bv[nf2][1]);
                MMA16816(acc[0][2 * nf2 + 1], a0, bv[nf2][2], bv[nf2][3]);
                MMA16816(acc[1][2 * nf2],     a1, bv[nf2][0], bv[nf2][1]);
                MMA16816(acc[1][2 * nf2 + 1], a1, bv[nf2][2], bv[nf2][3]);
            }
        }
        __syncthreads();
    }

    // ---- epilogue ----
    float* Cs = (float*)smem;   // out5 staging (64x128 fp32 = 32KB <= 48KB)
#pragma unroll
    for (int mf = 0; mf < 2; mf++) {
#pragma unroll
        for (int half = 0; half < 2; half++) {
            const int m = bm0 + wm * 32 + mf * 16 + (L >> 2) + half * 8;
            if (m >= M) continue;
            const float* g1r = ga.G1 ? ga.G1 + (size_t)ga.gi1[m] * ga.gs1 + ga.go1
                                     : nullptr;
            const float* g2r = ga.G2 ? ga.G2 + (size_t)ga.gi2[m] * ga.gs2 + ga.go2
                                     : nullptr;
            float* srowp = scat ? &C[(size_t)scat[m] * Nfull] : nullptr;
#pragma unroll
            for (int nf = 0; nf < 4; nf++) {
                const int col = bn0 + wn * 32 + nf * 8 + (L & 3) * 2;
                float v0 = acc[mf][nf][half * 2 + 0];
                float v1 = acc[mf][nf][half * 2 + 1];
                if (g1r) { v0 += g1r[col]; v1 += g1r[col + 1]; }
                if (g2r) { v0 += g2r[col]; v1 += g2r[col + 1]; }
                if (bias) { v0 += bias[col]; v1 += bias[col + 1]; }
                if (scat) {
                    v0 = fmaxf(v0, 0.f); v1 = fmaxf(v1, 0.f);
                    if (v0 != 0.0f) atomicAdd(srowp + col, v0);
                    if (v1 != 0.0f) atomicAdd(srowp + col + 1, v1);
                    continue;
                }
                const size_t o = (size_t)m * Nfull + col;
                if (C && accum) { v0 += C[o]; v1 += C[o + 1]; }
                if (relu) { v0 = fmaxf(v0, 0.f); v1 = fmaxf(v1, 0.f); }
                if (out5) {
                    Cs[(m - bm0) * 128 + (col - bn0)] = v0;
                    Cs[(m - bm0) * 128 + (col - bn0) + 1] = v1;
                    continue;
                }
                if (C) { C[o] = v0; C[o + 1] = v1; }
                if (Chi) {
                    __nv_bfloat16 h0, l0, h1, l1;
                    bf16_split(v0, h0, l0);
                    bf16_split(v1, h1, l1);
                    Chi[o] = h0; Chi[o + 1] = h1;
                    Clo[o] = l0; Clo[o + 1] = l1;
                }
            }
        }
    }

    // ---- fused final projection (128 -> 5), only when out5 set ----
    if (out5) {
        __syncthreads();
        if (tid < 64) {
            const int m = bm0 + tid;
            if (m < M) {
                const float* row = &Cs[tid * 128];
                float s0 = bd3[0], s1 = bd3[1], s2 = bd3[2], s3 = bd3[3], s4 = bd3[4];
#pragma unroll 8
                for (int k = 0; k < 128; k++) {
                    float x = row[k];
                    const float* w = &Wd3[k * 5];
                    s0 = fmaf(x, w[0], s0);
                    s1 = fmaf(x, w[1], s1);
                    s2 = fmaf(x, w[2], s2);
                    s3 = fmaf(x, w[3], s3);
                    s4 = fmaf(x, w[4], s4);
                }
                float* op = &out5[(size_t)m * 5];
                op[0] = s0; op[1] = s1; op[2] = s2; op[3] = s3; op[4] = s4;
            }
        }
    }
}

// ===========================================================================
// Batched weight transpose + split: W[K,N] fp32 -> Th/Tl [N, ldt] bf16 (padded)
// ===========================================================================
struct WJob { const float* W; int K, N, ldt; __nv_bfloat16* Th; __nv_bfloat16* Tl; };
struct WJobs { WJob j[18]; };

__global__ void wt_conv_all(WJobs jobs)
{
    const WJob jb = jobs.j[blockIdx.z];
    const int n0 = blockIdx.x * 32;
    const int k0 = blockIdx.y * 32;
    if (n0 >= jb.N || k0 >= jb.ldt) return;
    __shared__ float tile[32][33];
    const int tx = threadIdx.x, ty = threadIdx.y;  // 32x8
    for (int i = ty; i < 32; i += 8) {
        int k = k0 + i, n = n0 + tx;
        tile[i][tx] = (k < jb.K && n < jb.N) ? jb.W[(size_t)k * jb.N + n] : 0.0f;
    }
    __syncthreads();
    for (int i = ty; i < 32; i += 8) {
        int n = n0 + i, k = k0 + tx;
        if (n < jb.N && k < jb.ldt) {
            float x = tile[tx][i];
            __nv_bfloat16 hb, lb;
            bf16_split(x, hb, lb);
            jb.Th[(size_t)n * jb.ldt + k] = hb;
            jb.Tl[(size_t)n * jb.ldt + k] = lb;
        }
    }
}

// fp32 -> hi/lo planes; also re-zeroes the source (agg reuse across layers)
__global__ void act_conv_kernel(float* __restrict__ X,
                                __nv_bfloat16* __restrict__ Xh,
                                __nv_bfloat16* __restrict__ Xl, int n4)
{
    int i = blockIdx.x * 256 + threadIdx.x;
    if (i >= n4) return;
    float4 x = ((float4*)X)[i];
    __nv_bfloat16 hh[4], ll[4];
    bf16_split(x.x, hh[0], ll[0]);
    bf16_split(x.y, hh[1], ll[1]);
    bf16_split(x.z, hh[2], ll[2]);
    bf16_split(x.w, hh[3], ll[3]);
    *(uint2*)(Xh + (size_t)i * 4) = *(uint2*)hh;
    *(uint2*)(Xl + (size_t)i * 4) = *(uint2*)ll;
    ((float4*)X)[i] = make_float4(0.f, 0.f, 0.f, 0.f);
}

// ===========================================================================
// Elementwise / small kernels
// ===========================================================================

// one-hot h_node -> per-node type index (exact: h values are 0.0 or 1.0)
__global__ void type_kernel(const float* __restrict__ h_node,
                            int* __restrict__ ty, int N)
{
    int n = blockIdx.x * 256 + threadIdx.x;
    if (n >= N) return;
    int idx = 0;
#pragma unroll
    for (int k = 0; k < 16; k++)
        if (h_node[n * 16 + k] != 0.0f) idx = k;
    ty[n] = idx;
}

__global__ void init_node_kernel(const int* __restrict__ ty,
                                 const int* __restrict__ batch_node,
                                 const int* __restrict__ t,
                                 const float* __restrict__ Wne,
                                 float* __restrict__ hn,
                                 __nv_bfloat16* __restrict__ hn_h,
                                 __nv_bfloat16* __restrict__ hn_l,
                                 __nv_bfloat16* __restrict__ extn_h,
                                 __nv_bfloat16* __restrict__ extn_l)
{
    int row = blockIdx.x;
    int c = threadIdx.x;  // 256
    __shared__ float tn_s;
    __shared__ int ty_s;
    if (c == 0) { tn_s = (float)t[batch_node[row]]; ty_s = ty[row]; }
    __syncthreads();
    float tn = tn_s;
    float v;
    if (c < 240) {
        v = Wne[ty_s * 240 + c];   // one-hot row gather
    } else {
        const float step = 1000.0f / 15.0f;
        float dx = tn - (float)(c - 240) * step;
        v = expf((-0.5f / (step * step)) * dx * dx);
    }
    size_t idx = (size_t)row * 256 + c;
    hn[idx] = v;
    __nv_bfloat16 hb, lb; bf16_split(v, hb, lb);
    hn_h[idx] = hb; hn_l[idx] = lb;
    if (c < 64) {
        float ev = (c == 0) ? tn * (1.0f / 1000.0f) : 0.0f;
        __nv_bfloat16 eh, el; bf16_split(ev, eh, el);
        extn_h[(size_t)row * 64 + c] = eh;
        extn_l[(size_t)row * 64 + c] = el;
    }
}

// warp-per-edge: block = 256 threads = 8 edges. One-hot row gather for embed.
__global__ void init_edge_kernel(const int* __restrict__ ty,
                                 const float* __restrict__ pos,
                                 const int* __restrict__ ei,
                                 const int* __restrict__ batch_edge,
                                 const int* __restrict__ t,
                                 const float* __restrict__ Wee,
                                 float* __restrict__ he,
                                 __nv_bfloat16* __restrict__ he_h,
                                 __nv_bfloat16* __restrict__ he_l,
                                 __nv_bfloat16* __restrict__ exte_h,
                                 __nv_bfloat16* __restrict__ exte_l,
                                 int E)
{
    const int e = blockIdx.x * 8 + (threadIdx.x >> 5);
    const int L = threadIdx.x & 31;
    if (e >= E) return;
    const int s = ei[e], d = ei[E + e];
    const int ts = ty[s], td = ty[d];

    const float te = (float)t[batch_edge[e]];
    const float dx = pos[d * 3 + 0] - pos[s * 3 + 0];
    const float dy = pos[d * 3 + 1] - pos[s * 3 + 1];
    const float dz = pos[d * 3 + 2] - pos[s * 3 + 2];
    const float dd = sqrtf(dx * dx + dy * dy + dz * dz);

    const int c0 = L * 4;                 // this lane's 4 columns
    float v[4];
    if (c0 < 112) {
        float4 ws = *(const float4*)&Wee[ts * 112 + c0];
        float4 wd = *(const float4*)&Wee[(16 + td) * 112 + c0];
        v[0] = ws.x + wd.x; v[1] = ws.y + wd.y;
        v[2] = ws.z + wd.z; v[3] = ws.w + wd.w;
    } else {
        const float step = 1000.0f / 15.0f;
        const float cf = -0.5f / (step * step);
#pragma unroll
        for (int i = 0; i < 4; i++) {
            float dt = te - (float)(c0 + i - 112) * step;
            v[i] = expf(cf * dt * dt);
        }
    }
    const size_t idx = (size_t)e * 128 + c0;
    *(float4*)&he[idx] = make_float4(v[0], v[1], v[2], v[3]);
    __nv_bfloat16 hh[4], ll[4];
#pragma unroll
    for (int i = 0; i < 4; i++) bf16_split(v[i], hh[i], ll[i]);
    *(uint2*)&he_h[idx] = *(uint2*)hh;
    *(uint2*)&he_l[idx] = *(uint2*)ll;

    if (L < 16) {
        float ev[4];
#pragma unroll
        for (int i = 0; i < 4; i++) {
            int c = c0 + i;
            if (c < 16) {
                const float step = 10.0f / 15.0f;
                float dv = dd - (float)c * step;
                ev[i] = expf((-0.5f / (step * step)) * dv * dv);
            } else if (c == 16) {
                ev[i] = te * (1.0f / 1000.0f);
            } else {
                ev[i] = 0.0f;
            }
        }
        __nv_bfloat16 eh[4], el[4];
#pragma unroll
        for (int i = 0; i < 4; i++) bf16_split(ev[i], eh[i], el[i]);
        const size_t eidx = (size_t)e * 64 + c0;
        *(uint2*)&exte_h[eidx] = *(uint2*)eh;
        *(uint2*)&exte_l[eidx] = *(uint2*)el;
    }
}

__global__ void zero_kernel(float* __restrict__ p, int n)
{
    int i = blockIdx.x * 256 + threadIdx.x;
    if (i < n) p[i] = 0.0f;
}

__global__ void sym_kernel(const float* __restrict__ he,
                           __nv_bfloat16* __restrict__ oh,
                           __nv_bfloat16* __restrict__ ol, int nh)
{
    size_t i = (size_t)blockIdx.x * 256 + threadIdx.x;
    if (i >= (size_t)nh * 128) return;
    float v = he[i] + he[i + (size_t)nh * 128];
    __nv_bfloat16 hb, lb; bf16_split(v, hb, lb);
    oh[i] = hb; ol[i] = lb;
}

// ===========================================================================
// Host side
// ===========================================================================
template <typename T>
static T* sym_addr(T* symbol)
{
    void* p = nullptr;
    cudaGetSymbolAddress(&p, (const void*)symbol);
    return (T*)p;
}

static SegList make_segs(int n,
                         const __nv_bfloat16* h0, const __nv_bfloat16* l0, const int* g0, int K0,
                         const __nv_bfloat16* h1 = nullptr, const __nv_bfloat16* l1 = nullptr,
                         const int* g1 = nullptr, int K1 = 0,
                         const __nv_bfloat16* h2 = nullptr, const __nv_bfloat16* l2 = nullptr,
                         const int* g2 = nullptr, int K2 = 0)
{
    SegList sl;
    sl.s[0] = {h0, l0, g0, K0, 0, 0};
    sl.s[1] = {h1, l1, g1, K1, 0, 0};
    sl.s[2] = {h2, l2, g2, K2, 0, 0};
    sl.s[3] = {h0, l0, nullptr, K0, 0, 0};
    sl.n = n;
    int off = 0;
    for (int i = 0; i < 3; i++) {
        if (i < n) { sl.s[i].off = off; sl.s[i].boff = off; off += sl.s[i].K; }
    }
    sl.Ktot = off;
    for (int i = n; i < 4; i++) sl.s[i].off = off;   // sentinel: never selected
    return sl;
}

static GAdd make_gadd(const float* G1 = nullptr, const int* gi1 = nullptr,
                      int gs1 = 0, int go1 = 0,
                      const float* G2 = nullptr, const int* gi2 = nullptr,
                      int gs2 = 0, int go2 = 0)
{
    return GAdd{G1, gi1, gs1, go1, G2, gi2, gs2, go2};
}

static void launch_tgemm(const SegList& segs,
                         const __nv_bfloat16* Bh, const __nv_bfloat16* Bl, int ldb,
                         const GAdd& ga,
                         const float* bias, float* C,
                         __nv_bfloat16* Ch, __nv_bfloat16* Cl,
                         int M, int Nfull, int relu, int accum,
                         const int* scat = nullptr,
                         const float* Wd3 = nullptr, const float* bd3 = nullptr,
                         float* out5 = nullptr)
{
    dim3 grid(Nfull / 128, (M + 63) / 64);
    tgemm_kernel<<<grid, 256, TG_SMEM_BYTES>>>(segs, Bh, Bl, ldb, ga, bias,
                                               C, Ch, Cl, M, Nfull, relu, accum,
                                               scat, Wd3, bd3, out5);
}

extern "C" void kernel_launch(void* const* d_in, const int* in_sizes, int n_in,
                              void* d_out, int out_size)
{
    cudaFuncSetAttribute(tgemm_kernel, cudaFuncAttributeMaxDynamicSharedMemorySize,
                         TG_SMEM_BYTES);

    const float* h_node     = (const float*)d_in[0];
    const float* pos        = (const float*)d_in[1];
    const int*   batch_node = (const int*)  d_in[2];
    const int*   ei         = (const int*)  d_in[3];
    const int*   batch_edge = (const int*)  d_in[4];
    const int*   t          = (const int*)  d_in[5];
    const float* Wne = (const float*)d_in[6];
    const float* Wee = (const float*)d_in[7];
    const float* We1 = (const float*)d_in[8];
    const float* be1 = (const float*)d_in[9];
    const float* We2 = (const float*)d_in[10];
    const float* be2 = (const float*)d_in[11];
    const float* Wm  = (const float*)d_in[12];
    const float* bm  = (const float*)d_in[13];
    const float* Wn1 = (const float*)d_in[14];
    const float* bn1 = (const float*)d_in[15];
    const float* Wn2 = (const float*)d_in[16];
    const float* bn2 = (const float*)d_in[17];
    const float* Wd1 = (const float*)d_in[18];
    const float* bd1 = (const float*)d_in[19];
    const float* Wd2 = (const float*)d_in[20];
    const float* bd2 = (const float*)d_in[21];
    const float* Wd3 = (const float*)d_in[22];
    const float* bd3 = (const float*)d_in[23];

    const int N  = in_sizes[0] / 16;   // 20000
    const int E  = in_sizes[4];        // 200000
    const int nh = E / 2;              // 100000
    const int* src = ei;
    const int* dst = ei + E;

    float* hn   = sym_addr(g_hn);
    float* he   = sym_addr(g_he);
    float* agg  = sym_addr(g_agg);
    float* P12Q = sym_addr(g_P12Q);
    float* R    = P12Q;   // decode reuse ([N,128])
    int*   ty   = sym_addr(g_ty);

    __nv_bfloat16 *hn_h = sym_addr(g_hn_h), *hn_l = sym_addr(g_hn_l);
    __nv_bfloat16 *he_h = sym_addr(g_he_h), *he_l = sym_addr(g_he_l);
    __nv_bfloat16 *hide_h = sym_addr(g_hide_h), *hide_l = sym_addr(g_hide_l);
    __nv_bfloat16 *agg_h = sym_addr(g_agg_h), *agg_l = sym_addr(g_agg_l);
    __nv_bfloat16 *hidn_h = sym_addr(g_hidn_h), *hidn_l = sym_addr(g_hidn_l);
    __nv_bfloat16 *exte_h = sym_addr(g_exte_h), *exte_l = sym_addr(g_exte_l);
    __nv_bfloat16 *extn_h = sym_addr(g_extn_h), *extn_l = sym_addr(g_extn_l);
    __nv_bfloat16 *symh = sym_addr(g_sym_h), *syml = sym_addr(g_sym_l);
    __nv_bfloat16 *dec1_h = sym_addr(g_dec1_h), *dec1_l = sym_addr(g_dec1_l);

    __nv_bfloat16 *We1t_h = sym_addr(g_We1t_h), *We1t_l = sym_addr(g_We1t_l);
    __nv_bfloat16 *We2t_h = sym_addr(g_We2t_h), *We2t_l = sym_addr(g_We2t_l);
    __nv_bfloat16 *Wmt_h  = sym_addr(g_Wmt_h),  *Wmt_l  = sym_addr(g_Wmt_l);
    __nv_bfloat16 *Wn1t_h = sym_addr(g_Wn1t_h), *Wn1t_l = sym_addr(g_Wn1t_l);
    __nv_bfloat16 *Wn2t_h = sym_addr(g_Wn2t_h), *Wn2t_l = sym_addr(g_Wn2t_l);
    __nv_bfloat16 *Wd1t_h = sym_addr(g_Wd1t_h), *Wd1t_l = sym_addr(g_Wd1t_l);
    __nv_bfloat16 *Wd2t_h = sym_addr(g_Wd2t_h), *Wd2t_l = sym_addr(g_Wd2t_l);
    __nv_bfloat16 *Wpq_h  = sym_addr(g_Wpq_h),  *Wpq_l  = sym_addr(g_Wpq_l);

    // --- weight transpose + split: ONE batched launch (18 jobs) ---
    {
        WJobs J;
        int q = 0;
        for (int l = 0; l < 2; l++) {
            const float* We1l = We1 + (size_t)l * 657 * 128;
            J.j[q++] = {We1l, 657, 128, 704,
                        We1t_h + (size_t)l * 128 * 704, We1t_l + (size_t)l * 128 * 704};
            J.j[q++] = {We2 + (size_t)l * 128 * 128, 128, 128, 128,
                        We2t_h + (size_t)l * 128 * 128, We2t_l + (size_t)l * 128 * 128};
            J.j[q++] = {Wm + (size_t)l * 384 * 256, 384, 256, 384,
                        Wmt_h + (size_t)l * 256 * 384, Wmt_l + (size_t)l * 256 * 384};
            J.j[q++] = {Wn1 + (size_t)l * 513 * 256, 513, 256, 576,
                        Wn1t_h + (size_t)l * 256 * 576, Wn1t_l + (size_t)l * 256 * 576};
            J.j[q++] = {Wn2 + (size_t)l * 256 * 256, 256, 256, 256,
                        Wn2t_h + (size_t)l * 256 * 256, Wn2t_l + (size_t)l * 256 * 256};
            __nv_bfloat16* ph = Wpq_h + (size_t)l * 512 * 256;
            __nv_bfloat16* pl = Wpq_l + (size_t)l * 512 * 256;
            J.j[q++] = {We1l + (size_t)128 * 128, 256, 128, 256, ph, pl};
            J.j[q++] = {We1l + (size_t)384 * 128, 256, 128, 256,
                        ph + (size_t)128 * 256, pl + (size_t)128 * 256};
            J.j[q++] = {Wm + (size_t)l * 384 * 256, 256, 256, 256,
                        ph + (size_t)256 * 256, pl + (size_t)256 * 256};
        }
        J.j[q++] = {Wd1, 384, 128, 384, Wd1t_h, Wd1t_l};
        J.j[q++] = {Wd2, 128, 128, 128, Wd2t_h, Wd2t_l};
        wt_conv_all<<<dim3(8, 22, 18), dim3(32, 8)>>>(J);
    }

    // --- embeddings (one-hot lookup) + geometric features ---
    type_kernel<<<(N + 255) / 256, 256>>>(h_node, ty, N);
    init_node_kernel<<<N, 256>>>(ty, batch_node, t, Wne, hn, hn_h, hn_l,
                                 extn_h, extn_l);
    init_edge_kernel<<<(E + 7) / 8, 256>>>(ty, pos, ei, batch_edge, t, Wee,
                                           he, he_h, he_l, exte_h, exte_l, E);

    const GAdd noG = make_gadd();

    // --- L = 2 NodeEdgeNet blocks ---
    for (int l = 0; l < 2; l++) {
        const float* be1l = be1 + (size_t)l * 128;
        const float* be2l = be2 + (size_t)l * 128;
        const float* bml  = bm  + (size_t)l * 256;
        const float* bn1l = bn1 + (size_t)l * 256;
        const float* bn2l = bn2 + (size_t)l * 256;

        const __nv_bfloat16* We1th = We1t_h + (size_t)l * 128 * 704;
        const __nv_bfloat16* We1tl = We1t_l + (size_t)l * 128 * 704;
        const __nv_bfloat16* We2th = We2t_h + (size_t)l * 128 * 128;
        const __nv_bfloat16* We2tl = We2t_l + (size_t)l * 128 * 128;
        const __nv_bfloat16* Wmth  = Wmt_h  + (size_t)l * 256 * 384;
        const __nv_bfloat16* Wmtl  = Wmt_l  + (size_t)l * 256 * 384;
        const __nv_bfloat16* Wn1th = Wn1t_h + (size_t)l * 256 * 576;
        const __nv_bfloat16* Wn1tl = Wn1t_l + (size_t)l * 256 * 576;
        const __nv_bfloat16* Wn2th = Wn2t_h + (size_t)l * 256 * 256;
        const __nv_bfloat16* Wn2tl = Wn2t_l + (size_t)l * 256 * 256;
        const __nv_bfloat16* Wpqh  = Wpq_h  + (size_t)l * 512 * 256;
        const __nv_bfloat16* Wpql  = Wpq_l  + (size_t)l * 512 * 256;

        // P12Q = hn @ [We1[128:384] | We1[384:640] | Wm[0:256]]  (N x 512)
        launch_tgemm(make_segs(1, hn_h, hn_l, nullptr, 256),
                     Wpqh, Wpql, 256, noG, nullptr, P12Q, nullptr, nullptr,
                     N, 512, 0, 0);

        // hidden_e = relu(he@W0 + ext@W3 + P1[src] + P2[dst] + be1) -> planes
        {
            SegList se = make_segs(2,
                                   he_h, he_l, nullptr, 128,
                                   exte_h, exte_l, nullptr, 64);
            se.s[1].boff = 640;   // ext maps to We1 rows 640..704
            launch_tgemm(se, We1th, We1tl, 704,
                         make_gadd(P12Q, src, 512, 0, P12Q, dst, 512, 128),
                         be1l, nullptr, hide_h, hide_l, E, 128, 1, 0);
        }

        // agg must be zero before the first scatter (act_conv re-zeroes after)
        if (l == 0)
            zero_kernel<<<(N * 256 + 255) / 256, 256>>>(agg, N * 256);

        // h_e += hidden_e @ We2 + be2 (residual, fp32) + planes
        launch_tgemm(make_segs(1, hide_h, hide_l, nullptr, 128),
                     We2th, We2tl, 128, noG, be2l, he, he_h, he_l, E, 128, 0, 1);

        // agg[dst] += relu(he@Wm[256:384] + Q[src] + bm)  (fused scatter)
        {
            SegList sm = make_segs(1, he_h, he_l, nullptr, 128);
            sm.s[0].boff = 256;
            launch_tgemm(sm, Wmth, Wmtl, 384,
                         make_gadd(P12Q, src, 512, 256),
                         bml, agg, nullptr, nullptr, E, 256, 1, 0, dst);
        }

        // agg planes + re-zero agg for next layer
        act_conv_kernel<<<(N * 64 + 255) / 256, 256>>>(agg, agg_h, agg_l, N * 64);

        // hidden_n = relu([h_n | agg | ext_n] @ Wn1 + bn1) -> planes
        launch_tgemm(make_segs(3,
                         hn_h, hn_l, nullptr, 256,
                         agg_h, agg_l, nullptr, 256,
                         extn_h, extn_l, nullptr, 64),
                     Wn1th, Wn1tl, 576, noG, bn1l, nullptr, hidn_h, hidn_l,
                     N, 256, 1, 0);

        // h_n += hidden_n @ Wn2 + bn2 (residual, fp32) + planes
        launch_tgemm(make_segs(1, hidn_h, hidn_l, nullptr, 256),
                     Wn2th, Wn2tl, 256, noG, bn2l, hn, hn_h, hn_l, N, 256, 0, 1);
    }

    // --- decode ---
    // R = hn @ Wd1[128:384]  (node space; pair@W1 = R[src] + R[dst] by linearity)
    {
        SegList sr = make_segs(1, hn_h, hn_l, nullptr, 256);
        sr.s[0].boff = 128;
        launch_tgemm(sr, Wd1t_h, Wd1t_l, 384, noG, nullptr, R, nullptr, nullptr,
                     N, 128, 0, 0);
    }
    sym_kernel<<<(int)(((size_t)nh * 128 + 255) / 256), 256>>>(he, symh, syml, nh);

    // dec1 = relu(sym@Wd1[0:128] + R[src] + R[dst] + bd1) -> planes
    launch_tgemm(make_segs(1, symh, syml, nullptr, 128),
                 Wd1t_h, Wd1t_l, 384,
                 make_gadd(R, src, 128, 0, R, dst, 128, 0),
                 bd1, nullptr, dec1_h, dec1_l, nh, 128, 1, 0);

    // out = relu(dec1 @ Wd2 + bd2) @ Wd3 + bd3   (fused final projection)
    launch_tgemm(make_segs(1, dec1_h, dec1_l, nullptr, 128),
                 Wd2t_h, Wd2t_l, 128, noG, bd2, nullptr, nullptr, nullptr,
                 nh, 128, 1, 0, nullptr, Wd3, bd3, (float*)d_out);
}